// round 15
// baseline (speedup 1.0000x reference)
#include <cuda_runtime.h>
#include <cuda_bf16.h>
#include <cstdint>

#define N_NODES 50000
#define N_PAD   50048          // 782 * 64
#define N_EDGES 600000
#define D 128
#define BN_EPS 1e-5f
#define NB_SCAN 196            // 196 * 256 = 50176 >= N_NODES

// ---------------- scratch ----------------
__device__ __align__(256) __nv_bfloat16 g_zh[(size_t)N_PAD * D];     // (x+agg) hi
__device__ __align__(256) __nv_bfloat16 g_zl[(size_t)N_PAD * D];     // (x+agg) lo
__device__ __align__(256) __nv_bfloat16 g_h1h[(size_t)N_PAD * D];    // h1 hi
__device__ __align__(256) __nv_bfloat16 g_h1l[(size_t)N_PAD * D];    // h1 lo
__device__ __align__(256) float g_h2[(size_t)N_NODES * D];
__device__ __align__(256) __nv_bfloat16 g_w1h[D * D];  // W1^T hi [n][k]
__device__ __align__(256) __nv_bfloat16 g_w1l[D * D];
__device__ __align__(256) __nv_bfloat16 g_w2h[D * D];
__device__ __align__(256) __nv_bfloat16 g_w2l[D * D];
__device__ __align__(16) float g_sum[D];
__device__ __align__(16) float g_sumsq[D];
// CSR scratch
__device__ __align__(16) int g_cnt[N_NODES];
__device__ __align__(16) int g_off[N_NODES + 1];
__device__ __align__(16) int g_cur[N_NODES];
__device__ __align__(16) int g_elist[N_EDGES];
__device__ __align__(16) int g_bsum[256];

// ---------------- 1) init ----------------
__global__ void __launch_bounds__(256) init_all(const float* __restrict__ W1,
                                                const float* __restrict__ W2) {
    int b = blockIdx.x;
    int t = threadIdx.x;
    if (b < 49) {
        int i = b * 256 + t;
        if (i < N_NODES / 4)
            reinterpret_cast<int4*>(g_cnt)[i] = make_int4(0, 0, 0, 0);
    } else if (b == 49) {
        if (t < D) { g_sum[t] = 0.f; g_sumsq[t] = 0.f; }
    } else {
        int gid = (b - 50) * 256 + t;                // 0..16383
        int k = gid >> 7;
        int n = gid & 127;
        float v = W1[k * D + n];
        __nv_bfloat16 h = __float2bfloat16(v);
        g_w1h[n * D + k] = h;
        g_w1l[n * D + k] = __float2bfloat16(v - __bfloat162float(h));
        v = W2[k * D + n];
        h = __float2bfloat16(v);
        g_w2h[n * D + k] = h;
        g_w2l[n * D + k] = __float2bfloat16(v - __bfloat162float(h));
    }
}

// ---------------- 2) histogram of dst ----------------
__global__ void __launch_bounds__(256) hist_dst(const int* __restrict__ ei) {
    int i = blockIdx.x * 256 + threadIdx.x;
    if (i >= N_EDGES / 4) return;
    int4 d = reinterpret_cast<const int4*>(ei + N_EDGES)[i];
    atomicAdd(&g_cnt[d.x], 1);
    atomicAdd(&g_cnt[d.y], 1);
    atomicAdd(&g_cnt[d.z], 1);
    atomicAdd(&g_cnt[d.w], 1);
}

// ---------------- 3a) per-block sums (warp shuffles, 1 barrier) ----------------
__global__ void __launch_bounds__(256) scan_partial() {
    __shared__ int wsum[8];
    int t = threadIdx.x;
    int idx = blockIdx.x * 256 + t;
    int c = (idx < N_NODES) ? g_cnt[idx] : 0;
    #pragma unroll
    for (int m = 16; m; m >>= 1) c += __shfl_xor_sync(0xffffffffu, c, m);
    if ((t & 31) == 0) wsum[t >> 5] = c;
    __syncthreads();
    if (t == 0) {
        int s = 0;
        #pragma unroll
        for (int i = 0; i < 8; i++) s += wsum[i];
        g_bsum[blockIdx.x] = s;
    }
}

// ---------------- 3b) block prefix + intra-block scan (shuffles, 4 barriers) ----------------
__global__ void __launch_bounds__(256) scan_write() {
    __shared__ int sh[8];
    __shared__ int sbOff;
    int t = threadIdx.x;
    int lane = t & 31;
    int w = t >> 5;
    // block offset = sum g_bsum[0..bid)
    int v = (t < blockIdx.x) ? g_bsum[t] : 0;      // bid <= 195 < 256
    #pragma unroll
    for (int m = 16; m; m >>= 1) v += __shfl_xor_sync(0xffffffffu, v, m);
    if (lane == 0) sh[w] = v;
    __syncthreads();
    if (t == 0) {
        int s = 0;
        #pragma unroll
        for (int i = 0; i < 8; i++) s += sh[i];
        sbOff = s;
    }
    __syncthreads();
    int bOff = sbOff;
    // intra-block inclusive scan of counts
    int idx = blockIdx.x * 256 + t;
    int c = (idx < N_NODES) ? g_cnt[idx] : 0;
    int incl = c;
    #pragma unroll
    for (int m = 1; m < 32; m <<= 1) {
        int u = __shfl_up_sync(0xffffffffu, incl, m);
        if (lane >= m) incl += u;
    }
    __syncthreads();                // protect sh reuse
    if (lane == 31) sh[w] = incl;
    __syncthreads();
    int wpre = 0;
    #pragma unroll
    for (int i = 0; i < 8; i++) if (i < w) wpre += sh[i];
    int excl = bOff + wpre + incl - c;
    if (idx < N_NODES) {
        g_off[idx] = excl;
        g_cur[idx] = excl;
    }
    if (idx == N_NODES - 1) g_off[N_NODES] = N_EDGES;
}

// ---------------- 4) fill edge list ----------------
__global__ void __launch_bounds__(256) fill_elist(const int* __restrict__ ei) {
    int i = blockIdx.x * 256 + threadIdx.x;
    if (i >= N_EDGES / 2) return;
    int2 s = reinterpret_cast<const int2*>(ei)[i];
    int2 d = reinterpret_cast<const int2*>(ei + N_EDGES)[i];
    int p0 = atomicAdd(&g_cur[d.x], 1);
    g_elist[p0] = s.x;
    int p1 = atomicAdd(&g_cur[d.y], 1);
    g_elist[p1] = s.y;
}

// ---------------- 5) gather -> bf16 hi/lo ----------------
__global__ void __launch_bounds__(256) gather_agg(const float* __restrict__ x) {
    int warp = threadIdx.x >> 5;
    int lane = threadIdx.x & 31;
    int node = blockIdx.x * 8 + warp;
    if (node >= N_NODES) return;
    const float4* __restrict__ x4 = reinterpret_cast<const float4*>(x);
    int off = g_off[node];
    int end = g_off[node + 1];
    float4 a = x4[(size_t)node * 32 + lane];
    int i = off;
    for (; i + 4 <= end; i += 4) {
        int s0 = __ldg(&g_elist[i]);
        int s1 = __ldg(&g_elist[i + 1]);
        int s2 = __ldg(&g_elist[i + 2]);
        int s3 = __ldg(&g_elist[i + 3]);
        float4 v0 = x4[(size_t)s0 * 32 + lane];
        float4 v1 = x4[(size_t)s1 * 32 + lane];
        float4 v2 = x4[(size_t)s2 * 32 + lane];
        float4 v3 = x4[(size_t)s3 * 32 + lane];
        a.x += v0.x + v1.x + v2.x + v3.x;
        a.y += v0.y + v1.y + v2.y + v3.y;
        a.z += v0.z + v1.z + v2.z + v3.z;
        a.w += v0.w + v1.w + v2.w + v3.w;
    }
    for (; i < end; i++) {
        int s = __ldg(&g_elist[i]);
        float4 v = x4[(size_t)s * 32 + lane];
        a.x += v.x; a.y += v.y; a.z += v.z; a.w += v.w;
    }
    __nv_bfloat162 h01 = __floats2bfloat162_rn(a.x, a.y);
    __nv_bfloat162 h23 = __floats2bfloat162_rn(a.z, a.w);
    __nv_bfloat162 l01 = __floats2bfloat162_rn(a.x - __bfloat162float(h01.x),
                                               a.y - __bfloat162float(h01.y));
    __nv_bfloat162 l23 = __floats2bfloat162_rn(a.z - __bfloat162float(h23.x),
                                               a.w - __bfloat162float(h23.y));
    size_t p = (size_t)node * 32 + lane;
    reinterpret_cast<uint2*>(g_zh)[p] =
        make_uint2(*reinterpret_cast<uint32_t*>(&h01), *reinterpret_cast<uint32_t*>(&h23));
    reinterpret_cast<uint2*>(g_zl)[p] =
        make_uint2(*reinterpret_cast<uint32_t*>(&l01), *reinterpret_cast<uint32_t*>(&l23));
}

// ---------------- GEMM: 64x128 tile, bf16x3, 2-stage A pipeline ----------------
#define ASTRIDE 72
#define A_TILE (64 * ASTRIDE)     // bf16 elements per A half-buffer
#define B_TILE (128 * ASTRIDE)

#define MMA_BF16(d, A0, A1, A2, A3, B0, B1)                                   \
    asm volatile("mma.sync.aligned.m16n8k16.row.col.f32.bf16.bf16.f32 "       \
                 "{%0,%1,%2,%3}, {%4,%5,%6,%7}, {%8,%9}, {%0,%1,%2,%3};"      \
                 : "+f"(d[0]), "+f"(d[1]), "+f"(d[2]), "+f"(d[3])             \
                 : "r"(A0), "r"(A1), "r"(A2), "r"(A3), "r"(B0), "r"(B1))

#define LDSM_X4(r0, r1, r2, r3, addr)                                         \
    asm volatile("ldmatrix.sync.aligned.m8n8.x4.shared.b16 {%0,%1,%2,%3}, [%4];" \
                 : "=r"(r0), "=r"(r1), "=r"(r2), "=r"(r3) : "r"(addr))

#define CP_ASYNC16(smem_u32, gptr)                                            \
    asm volatile("cp.async.cg.shared.global [%0], [%1], 16;"                  \
                 :: "r"(smem_u32), "l"(gptr))

__global__ void __launch_bounds__(256, 3) gemm_mma(
        const __nv_bfloat16* __restrict__ AsrcH, const __nv_bfloat16* __restrict__ AsrcL,
        const __nv_bfloat16* __restrict__ WtH, const __nv_bfloat16* __restrict__ WtL,
        const float* __restrict__ bias,
        float* __restrict__ outF, __nv_bfloat16* __restrict__ outH, __nv_bfloat16* __restrict__ outL,
        int M, int relu, int do_stats) {
    extern __shared__ __align__(16) unsigned char smem_raw[];
    // layout (bf16 units): Ah[2][A_TILE] | Al[2][A_TILE] | Bh[B_TILE] | Bl[B_TILE]
    __nv_bfloat16* smem16 = reinterpret_cast<__nv_bfloat16*>(smem_raw);

    const int tid  = threadIdx.x;
    const int lane = tid & 31;
    const int wid  = tid >> 5;
    const int g    = lane >> 2;
    const int tig  = lane & 3;
    const int wm   = wid & 1;
    const int wn   = wid >> 1;
    const int rowBase = blockIdx.x * 64;

    const int a_row = (lane & 7) + ((lane >> 3) & 1) * 8;
    const int a_k   = (lane >> 4) * 8;
    const int b_n   = (lane & 7) + ((lane >> 4) & 1) * 8;
    const int b_k   = ((lane >> 3) & 1) * 8;

    const uint32_t smem_base = (uint32_t)__cvta_generic_to_shared(smem16);
    const uint32_t ah_base = smem_base;                      // + buf*A_TILE*2
    const uint32_t al_base = smem_base + 2 * A_TILE * 2;
    const uint32_t bh_base = smem_base + 4 * A_TILE * 2;
    const uint32_t bl_base = bh_base + B_TILE * 2;
    const uint32_t a_off = ((wm * 32 + a_row) * ASTRIDE + a_k) * 2;
    const uint32_t b_off = ((wn * 32 + b_n) * ASTRIDE + b_k) * 2;

    // staging index precompute
    const int af = tid;                 // 0..255 -> r=af>>3 (0..31) + it*32
    float acc[2][4][4];
    #pragma unroll
    for (int i = 0; i < 2; i++)
        #pragma unroll
        for (int j = 0; j < 4; j++)
            #pragma unroll
            for (int c = 0; c < 4; c++) acc[i][j][c] = 0.f;

    // ---- prologue: stage A0+B0 (group0), A1 (group1) ----
    #pragma unroll
    for (int it = 0; it < 2; it++) {
        int f = af + it * 256;
        int r = f >> 3;
        int c = (f & 7) * 8;
        int gr = rowBase + r;
        uint32_t so = (uint32_t)(r * ASTRIDE + c) * 2;
        CP_ASYNC16(ah_base + so, AsrcH + (size_t)gr * D + c);
        CP_ASYNC16(al_base + so, AsrcL + (size_t)gr * D + c);
    }
    #pragma unroll
    for (int it = 0; it < 4; it++) {
        int f = af + it * 256;
        int n = f >> 3;
        int c = (f & 7) * 8;
        uint32_t so = (uint32_t)(n * ASTRIDE + c) * 2;
        CP_ASYNC16(bh_base + so, WtH + n * D + c);
        CP_ASYNC16(bl_base + so, WtL + n * D + c);
    }
    asm volatile("cp.async.commit_group;");
    #pragma unroll
    for (int it = 0; it < 2; it++) {
        int f = af + it * 256;
        int r = f >> 3;
        int c = (f & 7) * 8;
        int gr = rowBase + r;
        uint32_t so = (uint32_t)(A_TILE + r * ASTRIDE + c) * 2;   // buffer 1
        CP_ASYNC16(ah_base + so, AsrcH + (size_t)gr * D + 64 + c);
        CP_ASYNC16(al_base + so, AsrcL + (size_t)gr * D + 64 + c);
    }
    asm volatile("cp.async.commit_group;");
    asm volatile("cp.async.wait_group 1;" ::: "memory");   // A0+B0 ready
    __syncthreads();

    #pragma unroll
    for (int half = 0; half < 2; half++) {
        const uint32_t abuf = (uint32_t)(half * A_TILE * 2);
        #pragma unroll
        for (int ks = 0; ks < 4; ks++) {
            const uint32_t kb = (uint32_t)(ks * 16) * 2;
            uint32_t ah[2][4], al[2][4];
            #pragma unroll
            for (int i = 0; i < 2; i++) {
                uint32_t off = abuf + a_off + (uint32_t)(i * 16 * ASTRIDE) * 2 + kb;
                LDSM_X4(ah[i][0], ah[i][1], ah[i][2], ah[i][3], ah_base + off);
                LDSM_X4(al[i][0], al[i][1], al[i][2], al[i][3], al_base + off);
            }
            #pragma unroll
            for (int j2 = 0; j2 < 2; j2++) {
                uint32_t off = b_off + (uint32_t)(j2 * 16 * ASTRIDE) * 2 + kb;
                uint32_t bh0, bh1, bh2, bh3, bl0, bl1, bl2, bl3;
                LDSM_X4(bh0, bh1, bh2, bh3, bh_base + off);
                LDSM_X4(bl0, bl1, bl2, bl3, bl_base + off);
                #pragma unroll
                for (int i = 0; i < 2; i++) {
                    MMA_BF16(acc[i][j2 * 2], ah[i][0], ah[i][1], ah[i][2], ah[i][3], bh0, bh1);
                    MMA_BF16(acc[i][j2 * 2], ah[i][0], ah[i][1], ah[i][2], ah[i][3], bl0, bl1);
                    MMA_BF16(acc[i][j2 * 2], al[i][0], al[i][1], al[i][2], al[i][3], bh0, bh1);
                    MMA_BF16(acc[i][j2 * 2 + 1], ah[i][0], ah[i][1], ah[i][2], ah[i][3], bh2, bh3);
                    MMA_BF16(acc[i][j2 * 2 + 1], ah[i][0], ah[i][1], ah[i][2], ah[i][3], bl2, bl3);
                    MMA_BF16(acc[i][j2 * 2 + 1], al[i][0], al[i][1], al[i][2], al[i][3], bh2, bh3);
                }
            }
        }
        if (half == 0) {
            // restage B for k-half 1 (A1 already in flight)
            __syncthreads();
            #pragma unroll
            for (int it = 0; it < 4; it++) {
                int f = af + it * 256;
                int n = f >> 3;
                int c = (f & 7) * 8;
                uint32_t so = (uint32_t)(n * ASTRIDE + c) * 2;
                CP_ASYNC16(bh_base + so, WtH + n * D + 64 + c);
                CP_ASYNC16(bl_base + so, WtL + n * D + 64 + c);
            }
            asm volatile("cp.async.commit_group;");
            asm volatile("cp.async.wait_group 0;" ::: "memory");   // A1 + B1
            __syncthreads();
        }
    }

    // ---- epilogue ----
    float* s_sum = reinterpret_cast<float*>(smem_raw);
    float* s_sq  = s_sum + 128;
    if (do_stats) {
        __syncthreads();
        if (tid < 256) s_sum[tid] = 0.f;
        __syncthreads();
    }

    #pragma unroll
    for (int j = 0; j < 4; j++) {
        const int col = wn * 32 + j * 8 + tig * 2;
        const float bb0 = bias[col], bb1 = bias[col + 1];
        float ls0 = 0.f, ls1 = 0.f, lq0 = 0.f, lq1 = 0.f;
        #pragma unroll
        for (int i = 0; i < 2; i++) {
            int row0 = rowBase + wm * 32 + i * 16 + g;
            float v00 = acc[i][j][0] + bb0, v01 = acc[i][j][1] + bb1;
            float v10 = acc[i][j][2] + bb0, v11 = acc[i][j][3] + bb1;
            if (relu) {
                v00 = fmaxf(v00, 0.f); v01 = fmaxf(v01, 0.f);
                v10 = fmaxf(v10, 0.f); v11 = fmaxf(v11, 0.f);
            }
            if (outF) {
                if (row0 < M) {
                    *reinterpret_cast<float2*>(outF + (size_t)row0 * D + col) = make_float2(v00, v01);
                    ls0 += v00; ls1 += v01;
                    lq0 = fmaf(v00, v00, lq0); lq1 = fmaf(v01, v01, lq1);
                }
                if (row0 + 8 < M) {
                    *reinterpret_cast<float2*>(outF + (size_t)(row0 + 8) * D + col) = make_float2(v10, v11);
                    ls0 += v10; ls1 += v11;
                    lq0 = fmaf(v10, v10, lq0); lq1 = fmaf(v11, v11, lq1);
                }
            } else {
                if (row0 < M) {
                    __nv_bfloat16 h0 = __float2bfloat16(v00), h1 = __float2bfloat16(v01);
                    __nv_bfloat16 l0 = __float2bfloat16(v00 - __bfloat162float(h0));
                    __nv_bfloat16 l1 = __float2bfloat16(v01 - __bfloat162float(h1));
                    *reinterpret_cast<__nv_bfloat162*>(outH + (size_t)row0 * D + col) = __nv_bfloat162(h0, h1);
                    *reinterpret_cast<__nv_bfloat162*>(outL + (size_t)row0 * D + col) = __nv_bfloat162(l0, l1);
                }
                if (row0 + 8 < M) {
                    __nv_bfloat16 h0 = __float2bfloat16(v10), h1 = __float2bfloat16(v11);
                    __nv_bfloat16 l0 = __float2bfloat16(v10 - __bfloat162float(h0));
                    __nv_bfloat16 l1 = __float2bfloat16(v11 - __bfloat162float(h1));
                    *reinterpret_cast<__nv_bfloat162*>(outH + (size_t)(row0 + 8) * D + col) = __nv_bfloat162(h0, h1);
                    *reinterpret_cast<__nv_bfloat162*>(outL + (size_t)(row0 + 8) * D + col) = __nv_bfloat162(l0, l1);
                }
            }
        }
        if (do_stats) {
            #pragma unroll
            for (int m = 4; m <= 16; m <<= 1) {
                ls0 += __shfl_xor_sync(0xffffffffu, ls0, m);
                ls1 += __shfl_xor_sync(0xffffffffu, ls1, m);
                lq0 += __shfl_xor_sync(0xffffffffu, lq0, m);
                lq1 += __shfl_xor_sync(0xffffffffu, lq1, m);
            }
            if (g == 0) {
                atomicAdd(&s_sum[col], ls0);
                atomicAdd(&s_sum[col + 1], ls1);
                atomicAdd(&s_sq[col], lq0);
                atomicAdd(&s_sq[col + 1], lq1);
            }
        }
    }

    if (do_stats) {
        __syncthreads();
        if (tid < 128) {
            atomicAdd(&g_sum[tid], s_sum[tid]);
            atomicAdd(&g_sumsq[tid], s_sq[tid]);
        }
    }
}

#define GEMM_SMEM ((4 * 64 + 2 * 128) * ASTRIDE * 2)   // 73728 B

// ---------------- bn_final ----------------
__global__ void __launch_bounds__(256) bn_final(const float* __restrict__ H,
                                                const float* __restrict__ X,
                                                const float* __restrict__ gamma,
                                                const float* __restrict__ beta,
                                                float* __restrict__ out) {
    __shared__ float s_scale[D];
    __shared__ float s_shift[D];
    int t = threadIdx.x;
    if (t < D) {
        float mean = g_sum[t] * (1.0f / N_NODES);
        float var = g_sumsq[t] * (1.0f / N_NODES) - mean * mean;
        float sc = gamma[t] * rsqrtf(var + BN_EPS);
        s_scale[t] = sc;
        s_shift[t] = beta[t] - mean * sc;
    }
    __syncthreads();
    const size_t n4 = (size_t)N_NODES * (D / 4);
    const size_t half = (n4 + 1) / 2;
    #pragma unroll
    for (int rep = 0; rep < 2; rep++) {
        size_t i = (size_t)blockIdx.x * 256 + t + rep * half;
        if (i >= n4) continue;
        int c4 = (int)(i & 31) << 2;
        float4 h = reinterpret_cast<const float4*>(H)[i];
        float4 x = reinterpret_cast<const float4*>(X)[i];
        float4 o;
        o.x = fmaf(h.x, s_scale[c4 + 0], s_shift[c4 + 0]) + x.x;
        o.y = fmaf(h.y, s_scale[c4 + 1], s_shift[c4 + 1]) + x.y;
        o.z = fmaf(h.z, s_scale[c4 + 2], s_shift[c4 + 2]) + x.z;
        o.w = fmaf(h.w, s_scale[c4 + 3], s_shift[c4 + 3]) + x.w;
        reinterpret_cast<float4*>(out)[i] = o;
    }
}

// ---------------- launcher ----------------
extern "C" void kernel_launch(void* const* d_in, const int* in_sizes, int n_in,
                              void* d_out, int out_size) {
    const float* x = (const float*)d_in[0];
    const int* ei = (const int*)d_in[1];
    const float* W1 = (const float*)d_in[2];
    const float* b1 = (const float*)d_in[3];
    const float* W2 = (const float*)d_in[4];
    const float* b2 = (const float*)d_in[5];
    const float* gamma = (const float*)d_in[6];
    const float* beta = (const float*)d_in[7];
    float* out = (float*)d_out;

    float* h2;   cudaGetSymbolAddress((void**)&h2,  g_h2);
    __nv_bfloat16 *zh, *zl, *h1h, *h1l, *w1h, *w1l, *w2h, *w2l;
    cudaGetSymbolAddress((void**)&zh,  g_zh);
    cudaGetSymbolAddress((void**)&zl,  g_zl);
    cudaGetSymbolAddress((void**)&h1h, g_h1h);
    cudaGetSymbolAddress((void**)&h1l, g_h1l);
    cudaGetSymbolAddress((void**)&w1h, g_w1h);
    cudaGetSymbolAddress((void**)&w1l, g_w1l);
    cudaGetSymbolAddress((void**)&w2h, g_w2h);
    cudaGetSymbolAddress((void**)&w2l, g_w2l);

    cudaFuncSetAttribute(gemm_mma, cudaFuncAttributeMaxDynamicSharedMemorySize, GEMM_SMEM);

    const int n4 = N_NODES * (D / 4);
    const int bnBlocks = ((n4 + 1) / 2 + 255) / 256;
    const int gemmBlocks = N_PAD / 64;   // 782

    init_all<<<114, 256>>>(W1, W2);
    hist_dst<<<(N_EDGES / 4 + 255) / 256, 256>>>(ei);
    scan_partial<<<NB_SCAN, 256>>>();
    scan_write<<<NB_SCAN, 256>>>();
    fill_elist<<<(N_EDGES / 2 + 255) / 256, 256>>>(ei);
    gather_agg<<<(N_NODES + 7) / 8, 256>>>(x);
    gemm_mma<<<gemmBlocks, 256, GEMM_SMEM>>>(zh, zl, w1h, w1l, b1,
                                             nullptr, h1h, h1l, N_NODES, 1, 0);
    gemm_mma<<<gemmBlocks, 256, GEMM_SMEM>>>(h1h, h1l, w2h, w2l, b2,
                                             h2, nullptr, nullptr, N_NODES, 0, 1);
    bn_final<<<bnBlocks, 256>>>(h2, x, gamma, beta, out);
}

// round 16
// speedup vs baseline: 1.0182x; 1.0182x over previous
#include <cuda_runtime.h>
#include <cuda_bf16.h>
#include <cstdint>

#define N_NODES 50000
#define N_PAD   50048          // 782 * 64
#define N_EDGES 600000
#define D 128
#define BN_EPS 1e-5f
#define NB_SCAN 196            // 196 * 256 = 50176 >= N_NODES

// ---------------- scratch ----------------
__device__ __align__(256) __nv_bfloat16 g_zh[(size_t)N_PAD * D];     // (x+agg) hi
__device__ __align__(256) __nv_bfloat16 g_zl[(size_t)N_PAD * D];     // (x+agg) lo
__device__ __align__(256) __nv_bfloat16 g_h1h[(size_t)N_PAD * D];    // h1 hi
__device__ __align__(256) __nv_bfloat16 g_h1l[(size_t)N_PAD * D];    // h1 lo
__device__ __align__(256) float g_h2[(size_t)N_NODES * D];
__device__ __align__(256) __nv_bfloat16 g_w1h[D * D];  // W1^T hi [n][k]
__device__ __align__(256) __nv_bfloat16 g_w1l[D * D];
__device__ __align__(256) __nv_bfloat16 g_w2h[D * D];
__device__ __align__(256) __nv_bfloat16 g_w2l[D * D];
__device__ __align__(16) float g_sum[D];
__device__ __align__(16) float g_sumsq[D];
// CSR scratch
__device__ __align__(16) int g_cnt[N_NODES];
__device__ __align__(16) int g_off[N_NODES + 1];
__device__ __align__(16) int g_cur[N_NODES];
__device__ __align__(16) int g_elist[N_EDGES];
__device__ __align__(16) int g_bsum[256];

// ---------------- 1) init ----------------
__global__ void __launch_bounds__(256) init_all(const float* __restrict__ W1,
                                                const float* __restrict__ W2) {
    int b = blockIdx.x;
    int t = threadIdx.x;
    if (b < 49) {
        int i = b * 256 + t;
        if (i < N_NODES / 4)
            reinterpret_cast<int4*>(g_cnt)[i] = make_int4(0, 0, 0, 0);
    } else if (b == 49) {
        if (t < D) { g_sum[t] = 0.f; g_sumsq[t] = 0.f; }
    } else {
        int gid = (b - 50) * 256 + t;                // 0..16383
        int k = gid >> 7;
        int n = gid & 127;
        float v = W1[k * D + n];
        __nv_bfloat16 h = __float2bfloat16(v);
        g_w1h[n * D + k] = h;
        g_w1l[n * D + k] = __float2bfloat16(v - __bfloat162float(h));
        v = W2[k * D + n];
        h = __float2bfloat16(v);
        g_w2h[n * D + k] = h;
        g_w2l[n * D + k] = __float2bfloat16(v - __bfloat162float(h));
    }
}

// ---------------- 2) histogram of dst ----------------
__global__ void __launch_bounds__(256) hist_dst(const int* __restrict__ ei) {
    int i = blockIdx.x * 256 + threadIdx.x;
    if (i >= N_EDGES / 4) return;
    int4 d = reinterpret_cast<const int4*>(ei + N_EDGES)[i];
    atomicAdd(&g_cnt[d.x], 1);
    atomicAdd(&g_cnt[d.y], 1);
    atomicAdd(&g_cnt[d.z], 1);
    atomicAdd(&g_cnt[d.w], 1);
}

// ---------------- 3a) per-block sums (warp shuffles) ----------------
__global__ void __launch_bounds__(256) scan_partial() {
    __shared__ int wsum[8];
    int t = threadIdx.x;
    int idx = blockIdx.x * 256 + t;
    int c = (idx < N_NODES) ? g_cnt[idx] : 0;
    #pragma unroll
    for (int m = 16; m; m >>= 1) c += __shfl_xor_sync(0xffffffffu, c, m);
    if ((t & 31) == 0) wsum[t >> 5] = c;
    __syncthreads();
    if (t == 0) {
        int s = 0;
        #pragma unroll
        for (int i = 0; i < 8; i++) s += wsum[i];
        g_bsum[blockIdx.x] = s;
    }
}

// ---------------- 3b) block prefix + intra-block scan (shuffles) ----------------
__global__ void __launch_bounds__(256) scan_write() {
    __shared__ int sh[8];
    __shared__ int sbOff;
    int t = threadIdx.x;
    int lane = t & 31;
    int w = t >> 5;
    int v = (t < blockIdx.x) ? g_bsum[t] : 0;      // bid <= 195 < 256
    #pragma unroll
    for (int m = 16; m; m >>= 1) v += __shfl_xor_sync(0xffffffffu, v, m);
    if (lane == 0) sh[w] = v;
    __syncthreads();
    if (t == 0) {
        int s = 0;
        #pragma unroll
        for (int i = 0; i < 8; i++) s += sh[i];
        sbOff = s;
    }
    __syncthreads();
    int bOff = sbOff;
    int idx = blockIdx.x * 256 + t;
    int c = (idx < N_NODES) ? g_cnt[idx] : 0;
    int incl = c;
    #pragma unroll
    for (int m = 1; m < 32; m <<= 1) {
        int u = __shfl_up_sync(0xffffffffu, incl, m);
        if (lane >= m) incl += u;
    }
    __syncthreads();                // protect sh reuse
    if (lane == 31) sh[w] = incl;
    __syncthreads();
    int wpre = 0;
    #pragma unroll
    for (int i = 0; i < 8; i++) if (i < w) wpre += sh[i];
    int excl = bOff + wpre + incl - c;
    if (idx < N_NODES) {
        g_off[idx] = excl;
        g_cur[idx] = excl;
    }
    if (idx == N_NODES - 1) g_off[N_NODES] = N_EDGES;
}

// ---------------- 4) fill edge list ----------------
__global__ void __launch_bounds__(256) fill_elist(const int* __restrict__ ei) {
    int i = blockIdx.x * 256 + threadIdx.x;
    if (i >= N_EDGES / 2) return;
    int2 s = reinterpret_cast<const int2*>(ei)[i];
    int2 d = reinterpret_cast<const int2*>(ei + N_EDGES)[i];
    int p0 = atomicAdd(&g_cur[d.x], 1);
    g_elist[p0] = s.x;
    int p1 = atomicAdd(&g_cur[d.y], 1);
    g_elist[p1] = s.y;
}

// ---------------- 5) gather -> bf16 hi/lo ----------------
__global__ void __launch_bounds__(256) gather_agg(const float* __restrict__ x) {
    int warp = threadIdx.x >> 5;
    int lane = threadIdx.x & 31;
    int node = blockIdx.x * 8 + warp;
    if (node >= N_NODES) return;
    const float4* __restrict__ x4 = reinterpret_cast<const float4*>(x);
    int off = g_off[node];
    int end = g_off[node + 1];
    float4 a = x4[(size_t)node * 32 + lane];
    int i = off;
    for (; i + 4 <= end; i += 4) {
        int s0 = __ldg(&g_elist[i]);
        int s1 = __ldg(&g_elist[i + 1]);
        int s2 = __ldg(&g_elist[i + 2]);
        int s3 = __ldg(&g_elist[i + 3]);
        float4 v0 = x4[(size_t)s0 * 32 + lane];
        float4 v1 = x4[(size_t)s1 * 32 + lane];
        float4 v2 = x4[(size_t)s2 * 32 + lane];
        float4 v3 = x4[(size_t)s3 * 32 + lane];
        a.x += v0.x + v1.x + v2.x + v3.x;
        a.y += v0.y + v1.y + v2.y + v3.y;
        a.z += v0.z + v1.z + v2.z + v3.z;
        a.w += v0.w + v1.w + v2.w + v3.w;
    }
    for (; i < end; i++) {
        int s = __ldg(&g_elist[i]);
        float4 v = x4[(size_t)s * 32 + lane];
        a.x += v.x; a.y += v.y; a.z += v.z; a.w += v.w;
    }
    __nv_bfloat162 h01 = __floats2bfloat162_rn(a.x, a.y);
    __nv_bfloat162 h23 = __floats2bfloat162_rn(a.z, a.w);
    __nv_bfloat162 l01 = __floats2bfloat162_rn(a.x - __bfloat162float(h01.x),
                                               a.y - __bfloat162float(h01.y));
    __nv_bfloat162 l23 = __floats2bfloat162_rn(a.z - __bfloat162float(h23.x),
                                               a.w - __bfloat162float(h23.y));
    size_t p = (size_t)node * 32 + lane;
    reinterpret_cast<uint2*>(g_zh)[p] =
        make_uint2(*reinterpret_cast<uint32_t*>(&h01), *reinterpret_cast<uint32_t*>(&h23));
    reinterpret_cast<uint2*>(g_zl)[p] =
        make_uint2(*reinterpret_cast<uint32_t*>(&l01), *reinterpret_cast<uint32_t*>(&l23));
}

// ---------------- GEMM: 64x128 tile, 8 warps (2 M x 4 N), bf16x3, cp.async (R14 config) ----------------
#define ASTRIDE 72

#define MMA_BF16(d, A0, A1, A2, A3, B0, B1)                                   \
    asm volatile("mma.sync.aligned.m16n8k16.row.col.f32.bf16.bf16.f32 "       \
                 "{%0,%1,%2,%3}, {%4,%5,%6,%7}, {%8,%9}, {%0,%1,%2,%3};"      \
                 : "+f"(d[0]), "+f"(d[1]), "+f"(d[2]), "+f"(d[3])             \
                 : "r"(A0), "r"(A1), "r"(A2), "r"(A3), "r"(B0), "r"(B1))

#define LDSM_X4(r0, r1, r2, r3, addr)                                         \
    asm volatile("ldmatrix.sync.aligned.m8n8.x4.shared.b16 {%0,%1,%2,%3}, [%4];" \
                 : "=r"(r0), "=r"(r1), "=r"(r2), "=r"(r3) : "r"(addr))

#define CP_ASYNC16(smem_u32, gptr)                                            \
    asm volatile("cp.async.cg.shared.global [%0], [%1], 16;"                  \
                 :: "r"(smem_u32), "l"(gptr))

__global__ void __launch_bounds__(256, 3) gemm_mma(
        const __nv_bfloat16* __restrict__ AsrcH, const __nv_bfloat16* __restrict__ AsrcL,
        const __nv_bfloat16* __restrict__ WtH, const __nv_bfloat16* __restrict__ WtL,
        const float* __restrict__ bias,
        float* __restrict__ outF, __nv_bfloat16* __restrict__ outH, __nv_bfloat16* __restrict__ outL,
        int M, int relu, int do_stats) {
    extern __shared__ __align__(16) unsigned char smem_raw[];
    __nv_bfloat16* Ah = reinterpret_cast<__nv_bfloat16*>(smem_raw);      // [64][ASTRIDE]
    __nv_bfloat16* Al = Ah + 64 * ASTRIDE;
    __nv_bfloat16* Bh = Al + 64 * ASTRIDE;                               // [128][ASTRIDE]
    __nv_bfloat16* Bl = Bh + 128 * ASTRIDE;

    const int tid  = threadIdx.x;
    const int lane = tid & 31;
    const int wid  = tid >> 5;
    const int g    = lane >> 2;
    const int tig  = lane & 3;
    const int wm   = wid & 1;
    const int wn   = wid >> 1;
    const int rowBase = blockIdx.x * 64;

    const int a_row = (lane & 7) + ((lane >> 3) & 1) * 8;
    const int a_k   = (lane >> 4) * 8;
    const int b_n   = (lane & 7) + ((lane >> 4) & 1) * 8;
    const int b_k   = ((lane >> 3) & 1) * 8;

    const uint32_t ah_base = (uint32_t)__cvta_generic_to_shared(Ah);
    const uint32_t al_base = (uint32_t)__cvta_generic_to_shared(Al);
    const uint32_t bh_base = (uint32_t)__cvta_generic_to_shared(Bh);
    const uint32_t bl_base = (uint32_t)__cvta_generic_to_shared(Bl);
    const uint32_t a_off = ((wm * 32 + a_row) * ASTRIDE + a_k) * 2;
    const uint32_t b_off = ((wn * 32 + b_n) * ASTRIDE + b_k) * 2;

    float acc[2][4][4];
    #pragma unroll
    for (int i = 0; i < 2; i++)
        #pragma unroll
        for (int j = 0; j < 4; j++)
            #pragma unroll
            for (int c = 0; c < 4; c++) acc[i][j][c] = 0.f;

    for (int k0 = 0; k0 < 128; k0 += 64) {
        if (k0) __syncthreads();

        #pragma unroll
        for (int it = 0; it < 2; it++) {
            int f = tid + it * 256;
            int r = f >> 3;
            int c = (f & 7) * 8;
            int gr = rowBase + r;
            uint32_t so = (uint32_t)(r * ASTRIDE + c) * 2;
            CP_ASYNC16(ah_base + so, AsrcH + (size_t)gr * D + k0 + c);
            CP_ASYNC16(al_base + so, AsrcL + (size_t)gr * D + k0 + c);
        }
        #pragma unroll
        for (int it = 0; it < 4; it++) {
            int f = tid + it * 256;
            int n = f >> 3;
            int c = (f & 7) * 8;
            uint32_t so = (uint32_t)(n * ASTRIDE + c) * 2;
            CP_ASYNC16(bh_base + so, WtH + n * D + k0 + c);
            CP_ASYNC16(bl_base + so, WtL + n * D + k0 + c);
        }
        asm volatile("cp.async.commit_group;");
        asm volatile("cp.async.wait_group 0;" ::: "memory");
        __syncthreads();

        #pragma unroll
        for (int ks = 0; ks < 4; ks++) {
            const uint32_t kb = (uint32_t)(ks * 16) * 2;
            uint32_t ah[2][4], al[2][4];
            #pragma unroll
            for (int i = 0; i < 2; i++) {
                uint32_t off = a_off + (uint32_t)(i * 16 * ASTRIDE) * 2 + kb;
                LDSM_X4(ah[i][0], ah[i][1], ah[i][2], ah[i][3], ah_base + off);
                LDSM_X4(al[i][0], al[i][1], al[i][2], al[i][3], al_base + off);
            }
            #pragma unroll
            for (int j2 = 0; j2 < 2; j2++) {
                uint32_t off = b_off + (uint32_t)(j2 * 16 * ASTRIDE) * 2 + kb;
                uint32_t bh0, bh1, bh2, bh3, bl0, bl1, bl2, bl3;
                LDSM_X4(bh0, bh1, bh2, bh3, bh_base + off);
                LDSM_X4(bl0, bl1, bl2, bl3, bl_base + off);
                #pragma unroll
                for (int i = 0; i < 2; i++) {
                    MMA_BF16(acc[i][j2 * 2], ah[i][0], ah[i][1], ah[i][2], ah[i][3], bh0, bh1);
                    MMA_BF16(acc[i][j2 * 2], ah[i][0], ah[i][1], ah[i][2], ah[i][3], bl0, bl1);
                    MMA_BF16(acc[i][j2 * 2], al[i][0], al[i][1], al[i][2], al[i][3], bh0, bh1);
                    MMA_BF16(acc[i][j2 * 2 + 1], ah[i][0], ah[i][1], ah[i][2], ah[i][3], bh2, bh3);
                    MMA_BF16(acc[i][j2 * 2 + 1], ah[i][0], ah[i][1], ah[i][2], ah[i][3], bl2, bl3);
                    MMA_BF16(acc[i][j2 * 2 + 1], al[i][0], al[i][1], al[i][2], al[i][3], bh2, bh3);
                }
            }
        }
    }

    // ---- epilogue ----
    float* s_sum = reinterpret_cast<float*>(smem_raw);
    float* s_sq  = s_sum + 128;
    if (do_stats) {
        __syncthreads();
        if (tid < 256) s_sum[tid] = 0.f;
        __syncthreads();
    }

    #pragma unroll
    for (int j = 0; j < 4; j++) {
        const int col = wn * 32 + j * 8 + tig * 2;
        const float bb0 = bias[col], bb1 = bias[col + 1];
        float ls0 = 0.f, ls1 = 0.f, lq0 = 0.f, lq1 = 0.f;
        #pragma unroll
        for (int i = 0; i < 2; i++) {
            int row0 = rowBase + wm * 32 + i * 16 + g;
            float v00 = acc[i][j][0] + bb0, v01 = acc[i][j][1] + bb1;
            float v10 = acc[i][j][2] + bb0, v11 = acc[i][j][3] + bb1;
            if (relu) {
                v00 = fmaxf(v00, 0.f); v01 = fmaxf(v01, 0.f);
                v10 = fmaxf(v10, 0.f); v11 = fmaxf(v11, 0.f);
            }
            if (outF) {
                if (row0 < M) {
                    *reinterpret_cast<float2*>(outF + (size_t)row0 * D + col) = make_float2(v00, v01);
                    ls0 += v00; ls1 += v01;
                    lq0 = fmaf(v00, v00, lq0); lq1 = fmaf(v01, v01, lq1);
                }
                if (row0 + 8 < M) {
                    *reinterpret_cast<float2*>(outF + (size_t)(row0 + 8) * D + col) = make_float2(v10, v11);
                    ls0 += v10; ls1 += v11;
                    lq0 = fmaf(v10, v10, lq0); lq1 = fmaf(v11, v11, lq1);
                }
            } else {
                if (row0 < M) {
                    __nv_bfloat16 h0 = __float2bfloat16(v00), h1 = __float2bfloat16(v01);
                    __nv_bfloat16 l0 = __float2bfloat16(v00 - __bfloat162float(h0));
                    __nv_bfloat16 l1 = __float2bfloat16(v01 - __bfloat162float(h1));
                    *reinterpret_cast<__nv_bfloat162*>(outH + (size_t)row0 * D + col) = __nv_bfloat162(h0, h1);
                    *reinterpret_cast<__nv_bfloat162*>(outL + (size_t)row0 * D + col) = __nv_bfloat162(l0, l1);
                }
                if (row0 + 8 < M) {
                    __nv_bfloat16 h0 = __float2bfloat16(v10), h1 = __float2bfloat16(v11);
                    __nv_bfloat16 l0 = __float2bfloat16(v10 - __bfloat162float(h0));
                    __nv_bfloat16 l1 = __float2bfloat16(v11 - __bfloat162float(h1));
                    *reinterpret_cast<__nv_bfloat162*>(outH + (size_t)(row0 + 8) * D + col) = __nv_bfloat162(h0, h1);
                    *reinterpret_cast<__nv_bfloat162*>(outL + (size_t)(row0 + 8) * D + col) = __nv_bfloat162(l0, l1);
                }
            }
        }
        if (do_stats) {
            #pragma unroll
            for (int m = 4; m <= 16; m <<= 1) {
                ls0 += __shfl_xor_sync(0xffffffffu, ls0, m);
                ls1 += __shfl_xor_sync(0xffffffffu, ls1, m);
                lq0 += __shfl_xor_sync(0xffffffffu, lq0, m);
                lq1 += __shfl_xor_sync(0xffffffffu, lq1, m);
            }
            if (g == 0) {
                atomicAdd(&s_sum[col], ls0);
                atomicAdd(&s_sum[col + 1], ls1);
                atomicAdd(&s_sq[col], lq0);
                atomicAdd(&s_sq[col + 1], lq1);
            }
        }
    }

    if (do_stats) {
        __syncthreads();
        if (tid < 128) {
            atomicAdd(&g_sum[tid], s_sum[tid]);
            atomicAdd(&g_sumsq[tid], s_sq[tid]);
        }
    }
}

#define GEMM_SMEM ((64 + 64 + 128 + 128) * ASTRIDE * 2)   // 55296 B

// ---------------- bn_final ----------------
__global__ void __launch_bounds__(256) bn_final(const float* __restrict__ H,
                                                const float* __restrict__ X,
                                                const float* __restrict__ gamma,
                                                const float* __restrict__ beta,
                                                float* __restrict__ out) {
    __shared__ float s_scale[D];
    __shared__ float s_shift[D];
    int t = threadIdx.x;
    if (t < D) {
        float mean = g_sum[t] * (1.0f / N_NODES);
        float var = g_sumsq[t] * (1.0f / N_NODES) - mean * mean;
        float sc = gamma[t] * rsqrtf(var + BN_EPS);
        s_scale[t] = sc;
        s_shift[t] = beta[t] - mean * sc;
    }
    __syncthreads();
    const size_t n4 = (size_t)N_NODES * (D / 4);
    const size_t half = (n4 + 1) / 2;
    #pragma unroll
    for (int rep = 0; rep < 2; rep++) {
        size_t i = (size_t)blockIdx.x * 256 + t + rep * half;
        if (i >= n4) continue;
        int c4 = (int)(i & 31) << 2;
        float4 h = reinterpret_cast<const float4*>(H)[i];
        float4 x = reinterpret_cast<const float4*>(X)[i];
        float4 o;
        o.x = fmaf(h.x, s_scale[c4 + 0], s_shift[c4 + 0]) + x.x;
        o.y = fmaf(h.y, s_scale[c4 + 1], s_shift[c4 + 1]) + x.y;
        o.z = fmaf(h.z, s_scale[c4 + 2], s_shift[c4 + 2]) + x.z;
        o.w = fmaf(h.w, s_scale[c4 + 3], s_shift[c4 + 3]) + x.w;
        reinterpret_cast<float4*>(out)[i] = o;
    }
}

// ---------------- launcher ----------------
extern "C" void kernel_launch(void* const* d_in, const int* in_sizes, int n_in,
                              void* d_out, int out_size) {
    const float* x = (const float*)d_in[0];
    const int* ei = (const int*)d_in[1];
    const float* W1 = (const float*)d_in[2];
    const float* b1 = (const float*)d_in[3];
    const float* W2 = (const float*)d_in[4];
    const float* b2 = (const float*)d_in[5];
    const float* gamma = (const float*)d_in[6];
    const float* beta = (const float*)d_in[7];
    float* out = (float*)d_out;

    float* h2;   cudaGetSymbolAddress((void**)&h2,  g_h2);
    __nv_bfloat16 *zh, *zl, *h1h, *h1l, *w1h, *w1l, *w2h, *w2l;
    cudaGetSymbolAddress((void**)&zh,  g_zh);
    cudaGetSymbolAddress((void**)&zl,  g_zl);
    cudaGetSymbolAddress((void**)&h1h, g_h1h);
    cudaGetSymbolAddress((void**)&h1l, g_h1l);
    cudaGetSymbolAddress((void**)&w1h, g_w1h);
    cudaGetSymbolAddress((void**)&w1l, g_w1l);
    cudaGetSymbolAddress((void**)&w2h, g_w2h);
    cudaGetSymbolAddress((void**)&w2l, g_w2l);

    cudaFuncSetAttribute(gemm_mma, cudaFuncAttributeMaxDynamicSharedMemorySize, GEMM_SMEM);

    const int n4 = N_NODES * (D / 4);
    const int bnBlocks = ((n4 + 1) / 2 + 255) / 256;
    const int gemmBlocks = N_PAD / 64;   // 782

    init_all<<<114, 256>>>(W1, W2);
    hist_dst<<<(N_EDGES / 4 + 255) / 256, 256>>>(ei);
    scan_partial<<<NB_SCAN, 256>>>();
    scan_write<<<NB_SCAN, 256>>>();
    fill_elist<<<(N_EDGES / 2 + 255) / 256, 256>>>(ei);
    gather_agg<<<(N_NODES + 7) / 8, 256>>>(x);
    gemm_mma<<<gemmBlocks, 256, GEMM_SMEM>>>(zh, zl, w1h, w1l, b1,
                                             nullptr, h1h, h1l, N_NODES, 1, 0);
    gemm_mma<<<gemmBlocks, 256, GEMM_SMEM>>>(h1h, h1l, w2h, w2l, b2,
                                             h2, nullptr, nullptr, N_NODES, 0, 1);
    bn_final<<<bnBlocks, 256>>>(h2, x, gamma, beta, out);
}